// round 8
// baseline (speedup 1.0000x reference)
#include <cuda_runtime.h>
#include <cuda_bf16.h>
#include <math.h>

// Problem constants
#define TT    16
#define BB    16384
#define D_IN  64
#define D_H   256
#define D_MID 64
#define D_OUT 4

// Tiling
#define BR      64           // batch rows per block
#define NTHR    256
#define HS_LD   260          // h_s row stride (floats), padded (16B aligned: 260*4=1040)
#define XS_LD   68           // x_s row stride
#define MS_LD   68           // mid_s row stride

// Pre-transposed weights (scratch; __device__ globals are the sanctioned scratch path)
__device__ float g_Wt_i2h[D_IN  * D_H ];  // [k=64 ][c=256]
__device__ float g_Wt_h2h[D_H   * D_H ];  // [k=256][c=256]
__device__ float g_Wt_h2o[D_H   * D_MID]; // [k=256][m=64 ]
__device__ float g_Wt_fc [D_MID * D_OUT]; // [m=64 ][o=4  ]

__global__ void prep_kernel(const float* __restrict__ Wi,  // [256][64]
                            const float* __restrict__ Wh,  // [256][256]
                            const float* __restrict__ Wo,  // [64][256]
                            const float* __restrict__ Wf)  // [4][64]
{
    int i = blockIdx.x * blockDim.x + threadIdx.x;  // 0 .. 65535
    if (i < D_IN * D_H) {
        int c = i % D_H, k = i / D_H;              // k<64
        g_Wt_i2h[k * D_H + c] = Wi[c * D_IN + k];
    }
    if (i < D_H * D_H) {
        int c = i % D_H, k = i / D_H;
        g_Wt_h2h[k * D_H + c] = Wh[c * D_H + k];
    }
    if (i < D_H * D_MID) {
        int m = i % D_MID, k = i / D_MID;
        g_Wt_h2o[k * D_MID + m] = Wo[m * D_H + k];
    }
    if (i < D_MID * D_OUT) {
        int o = i % D_OUT, m = i / D_OUT;
        g_Wt_fc[m * D_OUT + o] = Wf[o * D_MID + m];
    }
}

#define FMA4(A, S, W)                         \
    (A).x = fmaf((S), (W).x, (A).x);          \
    (A).y = fmaf((S), (W).y, (A).y);          \
    (A).z = fmaf((S), (W).z, (A).z);          \
    (A).w = fmaf((S), (W).w, (A).w);

__device__ __forceinline__ float4 tanh4(float4 v) {
    float4 r;
    r.x = tanhf(v.x); r.y = tanhf(v.y); r.z = tanhf(v.z); r.w = tanhf(v.w);
    return r;
}

// Dynamic smem layout
//   h_s   : BR x HS_LD  (row-major [row][k])
//   x_s   : BR x XS_LD
//   mid_s : BR x MS_LD
//   wfc_s : 256 floats (Wt_fc copy)
#define SMEM_FLOATS (BR*HS_LD + BR*XS_LD + BR*MS_LD + 256)

__global__ void __launch_bounds__(NTHR, 2)
rnn_persistent_kernel(const float* __restrict__ x,     // [T][B][64]
                      const float* __restrict__ hc1,   // [B][256]
                      const float* __restrict__ b_i2h, // [256]
                      const float* __restrict__ b_h2h, // [256]
                      const float* __restrict__ b_h2o, // [64]
                      const float* __restrict__ b_fc,  // [4]
                      float* __restrict__ out,
                      long long out_size)
{
    extern __shared__ float smem[];
    float* h_s   = smem;
    float* x_s   = h_s + BR * HS_LD;
    float* mid_s = x_s + BR * XS_LD;
    float* wfc_s = mid_s + BR * MS_LD;

    const int tid  = threadIdx.x;
    const int row0 = blockIdx.x * BR;

    // ---- one-time loads ----
    // hc1 tile -> h_s (row-major)
    {
        const float4* hg4 = (const float4*)(hc1 + (size_t)row0 * D_H);
        #pragma unroll
        for (int i = 0; i < (BR * D_H / 4) / NTHR; i++) {   // 16 iters
            int e4 = i * NTHR + tid;
            int r = e4 >> 6, k4 = e4 & 63;
            *(float4*)&h_s[r * HS_LD + k4 * 4] = hg4[e4];
        }
    }
    if (tid < D_MID * D_OUT) wfc_s[tid] = g_Wt_fc[tid];

    // stage-A thread mapping: 64 col-groups x 4 row-groups
    const int txA = tid & 63;       // col group: cols cA..cA+3
    const int tyA = tid >> 6;       // row group: rows tyA*16..+15
    const int cA  = txA * 4;
    float4 biasA;
    {
        float4 bi = *(const float4*)&b_i2h[cA];
        float4 bh = *(const float4*)&b_h2h[cA];
        biasA.x = bi.x + bh.x; biasA.y = bi.y + bh.y;
        biasA.z = bi.z + bh.z; biasA.w = bi.w + bh.w;
    }
    // stage-B mapping: 16 col-groups x 16 row-groups
    const int txB = tid & 15;       // cols mB..mB+3
    const int tyB = tid >> 4;       // rows tyB*4..+3
    const int mB  = txB * 4;
    const float4 biasB = *(const float4*)&b_h2o[mB];
    // stage-C mapping: 1 output per thread
    const int rC = tid >> 2;
    const int oC = tid & 3;
    const float biasC = b_fc[oC];

    __syncthreads();

    const long long SEQ_ELEMS = (long long)TT * BB * D_OUT;

    for (int t = 0; t < TT; t++) {
        // ---- load x_t tile ----
        {
            const float4* xg4 = (const float4*)(x + ((size_t)t * BB + row0) * D_IN);
            #pragma unroll
            for (int i = 0; i < (BR * D_IN / 4) / NTHR; i++) {  // 4 iters
                int e4 = i * NTHR + tid;
                int r = e4 >> 4, k4 = e4 & 15;
                *(float4*)&x_s[r * XS_LD + k4 * 4] = xg4[e4];
            }
        }
        __syncthreads();

        // ---- stage A: pre = x@Wi^T + h@Wh^T + b ; h_new = tanh(pre) ----
        float4 acc[16];
        #pragma unroll
        for (int r = 0; r < 16; r++) acc[r] = biasA;

        // x contribution (K = 64)
        #pragma unroll 2
        for (int k0 = 0; k0 < D_IN; k0 += 4) {
            const float4 w0 = *(const float4*)&g_Wt_i2h[(k0 + 0) * D_H + cA];
            const float4 w1 = *(const float4*)&g_Wt_i2h[(k0 + 1) * D_H + cA];
            const float4 w2 = *(const float4*)&g_Wt_i2h[(k0 + 2) * D_H + cA];
            const float4 w3 = *(const float4*)&g_Wt_i2h[(k0 + 3) * D_H + cA];
            #pragma unroll
            for (int r = 0; r < 16; r++) {
                float4 hv = *(float4*)&x_s[(tyA * 16 + r) * XS_LD + k0];
                FMA4(acc[r], hv.x, w0);
                FMA4(acc[r], hv.y, w1);
                FMA4(acc[r], hv.z, w2);
                FMA4(acc[r], hv.w, w3);
            }
        }
        // h contribution (K = 256)
        #pragma unroll 1
        for (int k0 = 0; k0 < D_H; k0 += 4) {
            const float4 w0 = *(const float4*)&g_Wt_h2h[(k0 + 0) * D_H + cA];
            const float4 w1 = *(const float4*)&g_Wt_h2h[(k0 + 1) * D_H + cA];
            const float4 w2 = *(const float4*)&g_Wt_h2h[(k0 + 2) * D_H + cA];
            const float4 w3 = *(const float4*)&g_Wt_h2h[(k0 + 3) * D_H + cA];
            #pragma unroll
            for (int r = 0; r < 16; r++) {
                float4 hv = *(float4*)&h_s[(tyA * 16 + r) * HS_LD + k0];
                FMA4(acc[r], hv.x, w0);
                FMA4(acc[r], hv.y, w1);
                FMA4(acc[r], hv.z, w2);
                FMA4(acc[r], hv.w, w3);
            }
        }
        #pragma unroll
        for (int r = 0; r < 16; r++) acc[r] = tanh4(acc[r]);

        __syncthreads();   // all stage-A reads of h_s done
        #pragma unroll
        for (int r = 0; r < 16; r++)
            *(float4*)&h_s[(tyA * 16 + r) * HS_LD + cA] = acc[r];
        __syncthreads();   // h_new visible

        // ---- stage B: mid = tanh(h_new @ Wo^T + b) ----
        float4 acc2[4];
        #pragma unroll
        for (int r = 0; r < 4; r++) acc2[r] = biasB;
        #pragma unroll 2
        for (int k0 = 0; k0 < D_H; k0 += 4) {
            const float4 w0 = *(const float4*)&g_Wt_h2o[(k0 + 0) * D_MID + mB];
            const float4 w1 = *(const float4*)&g_Wt_h2o[(k0 + 1) * D_MID + mB];
            const float4 w2 = *(const float4*)&g_Wt_h2o[(k0 + 2) * D_MID + mB];
            const float4 w3 = *(const float4*)&g_Wt_h2o[(k0 + 3) * D_MID + mB];
            #pragma unroll
            for (int r = 0; r < 4; r++) {
                float4 hv = *(float4*)&h_s[(tyB * 4 + r) * HS_LD + k0];
                FMA4(acc2[r], hv.x, w0);
                FMA4(acc2[r], hv.y, w1);
                FMA4(acc2[r], hv.z, w2);
                FMA4(acc2[r], hv.w, w3);
            }
        }
        #pragma unroll
        for (int r = 0; r < 4; r++)
            *(float4*)&mid_s[(tyB * 4 + r) * MS_LD + mB] = tanh4(acc2[r]);
        __syncthreads();   // mid visible

        // ---- stage C: out = mid @ Wfc^T + b ----
        {
            float accC = biasC;
            #pragma unroll
            for (int m = 0; m < D_MID; m++)
                accC = fmaf(mid_s[rC * MS_LD + m], wfc_s[m * D_OUT + oC], accC);
            out[((size_t)t * BB + row0 + rC) * D_OUT + oC] = accC;
        }
        __syncthreads();   // mid_s / h_s stable before next iteration
    }

    // ---- h_final ----
    if (out_size >= SEQ_ELEMS + (long long)BB * D_H) {
        float* hf = out + SEQ_ELEMS;
        #pragma unroll
        for (int i = 0; i < (BR * D_H / 4) / NTHR; i++) {
            int e4 = i * NTHR + tid;
            int r = e4 >> 6, k4 = e4 & 63;
            *(float4*)&hf[(size_t)(row0 + r) * D_H + k4 * 4] =
                *(float4*)&h_s[r * HS_LD + k4 * 4];
        }
    }
}

extern "C" void kernel_launch(void* const* d_in, const int* in_sizes, int n_in,
                              void* d_out, int out_size)
{
    const float* x     = (const float*)d_in[0];
    const float* hc1   = (const float*)d_in[1];
    const float* W_i2h = (const float*)d_in[2];
    const float* b_i2h = (const float*)d_in[3];
    const float* W_h2h = (const float*)d_in[4];
    const float* b_h2h = (const float*)d_in[5];
    const float* W_h2o = (const float*)d_in[6];
    const float* b_h2o = (const float*)d_in[7];
    const float* W_fc  = (const float*)d_in[8];
    const float* b_fc  = (const float*)d_in[9];
    float* out = (float*)d_out;

    // transpose weights into scratch (cheap, once per launch, capturable)
    prep_kernel<<<256, 256>>>(W_i2h, W_h2h, W_h2o, W_fc);

    const int smem_bytes = SMEM_FLOATS * (int)sizeof(float);
    cudaFuncSetAttribute(rnn_persistent_kernel,
                         cudaFuncAttributeMaxDynamicSharedMemorySize, smem_bytes);
    rnn_persistent_kernel<<<BB / BR, NTHR, smem_bytes>>>(
        x, hc1, b_i2h, b_h2h, b_h2o, b_fc, out, (long long)out_size);
}

// round 9
// speedup vs baseline: 1.0044x; 1.0044x over previous
#include <cuda_runtime.h>
#include <cuda_bf16.h>
#include <math.h>

// Problem constants
#define TT    16
#define BB    16384
#define D_IN  64
#define D_H   256
#define D_MID 64
#define D_OUT 4

// Tiling
#define BR      64           // batch rows per block
#define NTHR    256
#define HS_LD   260          // h_s row stride (floats), padded (16B aligned: 260*4=1040)
#define XS_LD   68           // x_s row stride
#define MS_LD   68           // mid_s row stride

// Pre-transposed weights (scratch; __device__ globals are the sanctioned scratch path)
__device__ float g_Wt_i2h[D_IN  * D_H ];  // [k=64 ][c=256]
__device__ float g_Wt_h2h[D_H   * D_H ];  // [k=256][c=256]
__device__ float g_Wt_h2o[D_H   * D_MID]; // [k=256][m=64 ]
__device__ float g_Wt_fc [D_MID * D_OUT]; // [m=64 ][o=4  ]

__global__ void prep_kernel(const float* __restrict__ Wi,  // [256][64]
                            const float* __restrict__ Wh,  // [256][256]
                            const float* __restrict__ Wo,  // [64][256]
                            const float* __restrict__ Wf)  // [4][64]
{
    int i = blockIdx.x * blockDim.x + threadIdx.x;  // 0 .. 65535
    if (i < D_IN * D_H) {
        int c = i % D_H, k = i / D_H;              // k<64
        g_Wt_i2h[k * D_H + c] = Wi[c * D_IN + k];
    }
    if (i < D_H * D_H) {
        int c = i % D_H, k = i / D_H;
        g_Wt_h2h[k * D_H + c] = Wh[c * D_H + k];
    }
    if (i < D_H * D_MID) {
        int m = i % D_MID, k = i / D_MID;
        g_Wt_h2o[k * D_MID + m] = Wo[m * D_H + k];
    }
    if (i < D_MID * D_OUT) {
        int o = i % D_OUT, m = i / D_OUT;
        g_Wt_fc[m * D_OUT + o] = Wf[o * D_MID + m];
    }
}

#define FMA4(A, S, W)                         \
    (A).x = fmaf((S), (W).x, (A).x);          \
    (A).y = fmaf((S), (W).y, (A).y);          \
    (A).z = fmaf((S), (W).z, (A).z);          \
    (A).w = fmaf((S), (W).w, (A).w);

__device__ __forceinline__ float4 tanh4(float4 v) {
    float4 r;
    r.x = tanhf(v.x); r.y = tanhf(v.y); r.z = tanhf(v.z); r.w = tanhf(v.w);
    return r;
}

// Dynamic smem layout
//   h_s   : BR x HS_LD  (row-major [row][k])
//   x_s   : BR x XS_LD
//   mid_s : BR x MS_LD
//   wfc_s : 256 floats (Wt_fc copy)
#define SMEM_FLOATS (BR*HS_LD + BR*XS_LD + BR*MS_LD + 256)

__global__ void __launch_bounds__(NTHR, 2)
rnn_persistent_kernel(const float* __restrict__ x,     // [T][B][64]
                      const float* __restrict__ hc1,   // [B][256]
                      const float* __restrict__ b_i2h, // [256]
                      const float* __restrict__ b_h2h, // [256]
                      const float* __restrict__ b_h2o, // [64]
                      const float* __restrict__ b_fc,  // [4]
                      float* __restrict__ out,
                      long long out_size)
{
    extern __shared__ float smem[];
    float* h_s   = smem;
    float* x_s   = h_s + BR * HS_LD;
    float* mid_s = x_s + BR * XS_LD;
    float* wfc_s = mid_s + BR * MS_LD;

    const int tid  = threadIdx.x;
    const int row0 = blockIdx.x * BR;

    // ---- one-time loads ----
    // hc1 tile -> h_s (row-major)
    {
        const float4* hg4 = (const float4*)(hc1 + (size_t)row0 * D_H);
        #pragma unroll
        for (int i = 0; i < (BR * D_H / 4) / NTHR; i++) {   // 16 iters
            int e4 = i * NTHR + tid;
            int r = e4 >> 6, k4 = e4 & 63;
            *(float4*)&h_s[r * HS_LD + k4 * 4] = hg4[e4];
        }
    }
    if (tid < D_MID * D_OUT) wfc_s[tid] = g_Wt_fc[tid];

    // stage-A thread mapping: 64 col-groups x 4 row-groups
    const int txA = tid & 63;       // col group: cols cA..cA+3
    const int tyA = tid >> 6;       // row group: rows tyA*16..+15
    const int cA  = txA * 4;
    float4 biasA;
    {
        float4 bi = *(const float4*)&b_i2h[cA];
        float4 bh = *(const float4*)&b_h2h[cA];
        biasA.x = bi.x + bh.x; biasA.y = bi.y + bh.y;
        biasA.z = bi.z + bh.z; biasA.w = bi.w + bh.w;
    }
    // stage-B mapping: 16 col-groups x 16 row-groups
    const int txB = tid & 15;       // cols mB..mB+3
    const int tyB = tid >> 4;       // rows tyB*4..+3
    const int mB  = txB * 4;
    const float4 biasB = *(const float4*)&b_h2o[mB];
    // stage-C mapping: 1 output per thread
    const int rC = tid >> 2;
    const int oC = tid & 3;
    const float biasC = b_fc[oC];

    __syncthreads();

    const long long SEQ_ELEMS = (long long)TT * BB * D_OUT;

    for (int t = 0; t < TT; t++) {
        // ---- load x_t tile ----
        {
            const float4* xg4 = (const float4*)(x + ((size_t)t * BB + row0) * D_IN);
            #pragma unroll
            for (int i = 0; i < (BR * D_IN / 4) / NTHR; i++) {  // 4 iters
                int e4 = i * NTHR + tid;
                int r = e4 >> 4, k4 = e4 & 15;
                *(float4*)&x_s[r * XS_LD + k4 * 4] = xg4[e4];
            }
        }
        __syncthreads();

        // ---- stage A: pre = x@Wi^T + h@Wh^T + b ; h_new = tanh(pre) ----
        float4 acc[16];
        #pragma unroll
        for (int r = 0; r < 16; r++) acc[r] = biasA;

        // x contribution (K = 64)
        #pragma unroll 2
        for (int k0 = 0; k0 < D_IN; k0 += 4) {
            const float4 w0 = *(const float4*)&g_Wt_i2h[(k0 + 0) * D_H + cA];
            const float4 w1 = *(const float4*)&g_Wt_i2h[(k0 + 1) * D_H + cA];
            const float4 w2 = *(const float4*)&g_Wt_i2h[(k0 + 2) * D_H + cA];
            const float4 w3 = *(const float4*)&g_Wt_i2h[(k0 + 3) * D_H + cA];
            #pragma unroll
            for (int r = 0; r < 16; r++) {
                float4 hv = *(float4*)&x_s[(tyA * 16 + r) * XS_LD + k0];
                FMA4(acc[r], hv.x, w0);
                FMA4(acc[r], hv.y, w1);
                FMA4(acc[r], hv.z, w2);
                FMA4(acc[r], hv.w, w3);
            }
        }
        // h contribution (K = 256)
        #pragma unroll 1
        for (int k0 = 0; k0 < D_H; k0 += 4) {
            const float4 w0 = *(const float4*)&g_Wt_h2h[(k0 + 0) * D_H + cA];
            const float4 w1 = *(const float4*)&g_Wt_h2h[(k0 + 1) * D_H + cA];
            const float4 w2 = *(const float4*)&g_Wt_h2h[(k0 + 2) * D_H + cA];
            const float4 w3 = *(const float4*)&g_Wt_h2h[(k0 + 3) * D_H + cA];
            #pragma unroll
            for (int r = 0; r < 16; r++) {
                float4 hv = *(float4*)&h_s[(tyA * 16 + r) * HS_LD + k0];
                FMA4(acc[r], hv.x, w0);
                FMA4(acc[r], hv.y, w1);
                FMA4(acc[r], hv.z, w2);
                FMA4(acc[r], hv.w, w3);
            }
        }
        #pragma unroll
        for (int r = 0; r < 16; r++) acc[r] = tanh4(acc[r]);

        __syncthreads();   // all stage-A reads of h_s done
        #pragma unroll
        for (int r = 0; r < 16; r++)
            *(float4*)&h_s[(tyA * 16 + r) * HS_LD + cA] = acc[r];
        __syncthreads();   // h_new visible

        // ---- stage B: mid = tanh(h_new @ Wo^T + b) ----
        float4 acc2[4];
        #pragma unroll
        for (int r = 0; r < 4; r++) acc2[r] = biasB;
        #pragma unroll 2
        for (int k0 = 0; k0 < D_H; k0 += 4) {
            const float4 w0 = *(const float4*)&g_Wt_h2o[(k0 + 0) * D_MID + mB];
            const float4 w1 = *(const float4*)&g_Wt_h2o[(k0 + 1) * D_MID + mB];
            const float4 w2 = *(const float4*)&g_Wt_h2o[(k0 + 2) * D_MID + mB];
            const float4 w3 = *(const float4*)&g_Wt_h2o[(k0 + 3) * D_MID + mB];
            #pragma unroll
            for (int r = 0; r < 4; r++) {
                float4 hv = *(float4*)&h_s[(tyB * 4 + r) * HS_LD + k0];
                FMA4(acc2[r], hv.x, w0);
                FMA4(acc2[r], hv.y, w1);
                FMA4(acc2[r], hv.z, w2);
                FMA4(acc2[r], hv.w, w3);
            }
        }
        #pragma unroll
        for (int r = 0; r < 4; r++)
            *(float4*)&mid_s[(tyB * 4 + r) * MS_LD + mB] = tanh4(acc2[r]);
        __syncthreads();   // mid visible

        // ---- stage C: out = mid @ Wfc^T + b ----
        {
            float accC = biasC;
            #pragma unroll
            for (int m = 0; m < D_MID; m++)
                accC = fmaf(mid_s[rC * MS_LD + m], wfc_s[m * D_OUT + oC], accC);
            out[((size_t)t * BB + row0 + rC) * D_OUT + oC] = accC;
        }
        __syncthreads();   // mid_s / h_s stable before next iteration
    }

    // ---- h_final ----
    if (out_size >= SEQ_ELEMS + (long long)BB * D_H) {
        float* hf = out + SEQ_ELEMS;
        #pragma unroll
        for (int i = 0; i < (BR * D_H / 4) / NTHR; i++) {
            int e4 = i * NTHR + tid;
            int r = e4 >> 6, k4 = e4 & 63;
            *(float4*)&hf[(size_t)(row0 + r) * D_H + k4 * 4] =
                *(float4*)&h_s[r * HS_LD + k4 * 4];
        }
    }
}

extern "C" void kernel_launch(void* const* d_in, const int* in_sizes, int n_in,
                              void* d_out, int out_size)
{
    const float* x     = (const float*)d_in[0];
    const float* hc1   = (const float*)d_in[1];
    const float* W_i2h = (const float*)d_in[2];
    const float* b_i2h = (const float*)d_in[3];
    const float* W_h2h = (const float*)d_in[4];
    const float* b_h2h = (const float*)d_in[5];
    const float* W_h2o = (const float*)d_in[6];
    const float* b_h2o = (const float*)d_in[7];
    const float* W_fc  = (const float*)d_in[8];
    const float* b_fc  = (const float*)d_in[9];
    float* out = (float*)d_out;

    // transpose weights into scratch (cheap, once per launch, capturable)
    prep_kernel<<<256, 256>>>(W_i2h, W_h2h, W_h2o, W_fc);

    const int smem_bytes = SMEM_FLOATS * (int)sizeof(float);
    cudaFuncSetAttribute(rnn_persistent_kernel,
                         cudaFuncAttributeMaxDynamicSharedMemorySize, smem_bytes);
    rnn_persistent_kernel<<<BB / BR, NTHR, smem_bytes>>>(
        x, hc1, b_i2h, b_h2h, b_h2o, b_fc, out, (long long)out_size);
}